// round 7
// baseline (speedup 1.0000x reference)
#include <cuda_runtime.h>
#include <cuda_fp16.h>
#include <math.h>
#include <stdint.h>

#define BB 128
#define SS 768
#define CC 384
#define MM (BB*SS)      // 98304 tokens

// ======================= low-level helpers (sm_80 ISA only) =======================
__device__ __forceinline__ uint32_t smem_to_u32(const void* smem_ptr) {
    uint32_t addr;
    asm("{ .reg .u64 tmp; cvta.to.shared.u64 tmp, %1; cvt.u32.u64 %0, tmp; }"
        : "=r"(addr) : "l"(smem_ptr));
    return addr;
}

#define CP_ASYNC16(dst32, gptr) \
    asm volatile("cp.async.cg.shared.global [%0], [%1], 16;" :: "r"(dst32), "l"(gptr) : "memory")
#define CP_COMMIT() asm volatile("cp.async.commit_group;" ::: "memory")

#define LDMATRIX_X4(r0, r1, r2, r3, addr) \
    asm volatile("ldmatrix.sync.aligned.m8n8.x4.shared.b16 {%0,%1,%2,%3}, [%4];" \
        : "=r"(r0), "=r"(r1), "=r"(r2), "=r"(r3) : "r"(addr))

#define MMA_F16(d, a, b0, b1) \
    asm volatile("mma.sync.aligned.m16n8k16.row.col.f32.f16.f16.f32 " \
        "{%0,%1,%2,%3}, {%4,%5,%6,%7}, {%8,%9}, {%0,%1,%2,%3};" \
        : "+f"((d)[0]), "+f"((d)[1]), "+f"((d)[2]), "+f"((d)[3]) \
        : "r"((a)[0]), "r"((a)[1]), "r"((a)[2]), "r"((a)[3]), "r"(b0), "r"(b1))

// ======================= scratch (device globals) =======================
__device__ float g_t0f[(size_t)MM * CC];                 // tokens fp32 (resid; also t3)
__device__ __half g_t0h[(size_t)MM * CC];                // tokens fp16 (GEMM A)
__device__ float g_t1f[(size_t)MM * CC];                 // attn-block output / final LN out
__device__ float g_t2f[(size_t)MM * CC];                 // post-LN1 fp32 (resid for MLP2)
__device__ __half g_t2h[(size_t)MM * CC];                // post-LN1 fp16
__device__ __half g_qkvh[(size_t)MM * 3456];             // mega qkv fp16 (aliased by mlp hidden)
__device__ __half g_aoh[(size_t)MM * 1152];              // concat attention outputs fp16
__device__ float g_bsum[CC];                             // bo0+bo1+bo2
#define WTOTAL 2949120
__device__ __half g_wh[WTOTAL];                          // transposed fp16 weights

// ======================= transposes / weight prep =======================
// x (B, C, S) -> t0 (B*S, C) fp32 + fp16
__global__ void transpose_in_kernel(const float* __restrict__ x, float* __restrict__ t0f,
                                    __half* __restrict__ t0h) {
    __shared__ float tile[32][33];
    int b = blockIdx.z;
    int s0 = blockIdx.x * 32;
    int c0 = blockIdx.y * 32;
    int tx = threadIdx.x, ty = threadIdx.y;  // (32,8)
    const float* xp = x + (size_t)b * CC * SS;
#pragma unroll
    for (int yy = 0; yy < 32; yy += 8)
        tile[ty + yy][tx] = xp[(size_t)(c0 + ty + yy) * SS + s0 + tx];
    __syncthreads();
    size_t ob = (size_t)b * SS * CC;
#pragma unroll
    for (int yy = 0; yy < 32; yy += 8) {
        float v = tile[tx][ty + yy];
        size_t o = ob + (size_t)(s0 + ty + yy) * CC + c0 + tx;
        t0f[o] = v;
        t0h[o] = __float2half(v);
    }
}

// t (B*S, C) -> out (B, C, S)
__global__ void transpose_out_kernel(const float* __restrict__ t, float* __restrict__ out) {
    __shared__ float tile[32][33];
    int b = blockIdx.z;
    int s0 = blockIdx.x * 32;
    int c0 = blockIdx.y * 32;
    int tx = threadIdx.x, ty = threadIdx.y;
    const float* tp = t + (size_t)b * SS * CC;
#pragma unroll
    for (int yy = 0; yy < 32; yy += 8)
        tile[ty + yy][tx] = tp[(size_t)(s0 + ty + yy) * CC + c0 + tx];
    __syncthreads();
    float* op = out + (size_t)b * CC * SS;
#pragma unroll
    for (int yy = 0; yy < 32; yy += 8)
        op[(size_t)(c0 + ty + yy) * SS + s0 + tx] = tile[tx][ty + yy];
}

// W [Ksrc, N] fp32 -> T [N, *] fp16 at row-stride dstStride (transpose + convert)
// grid.y covers Ksrc/32, grid.x covers N/32; caller pre-offsets T for column placement.
__global__ void wconv_kernel(const float* __restrict__ W, __half* __restrict__ T,
                             int N, int dstStride) {
    __shared__ float tile[32][33];
    int n0 = blockIdx.x * 32;
    int k0 = blockIdx.y * 32;
    int tx = threadIdx.x, ty = threadIdx.y;  // (32,8)
#pragma unroll
    for (int yy = 0; yy < 32; yy += 8)
        tile[ty + yy][tx] = W[(size_t)(k0 + ty + yy) * N + n0 + tx];
    __syncthreads();
#pragma unroll
    for (int yy = 0; yy < 32; yy += 8)
        T[(size_t)(n0 + ty + yy) * dstStride + k0 + tx] = __float2half(tile[tx][ty + yy]);
}

__global__ void bias_sum_kernel(const float* __restrict__ b0, const float* __restrict__ b1,
                                const float* __restrict__ b2, float* __restrict__ bs) {
    int c = threadIdx.x + blockIdx.x * blockDim.x;
    if (c < CC) bs[c] = b0[c] + b1[c] + b2[c];
}

// ======================= fp16 warp-mma GEMM (3-stage cp.async) =======================
// C[M,N] = A[M,K] * B^T, A [M,K] fp16, B [N,K] fp16 (both K-major).
// Block tile 128x128, BK=64 (one 128B smem row, 8x16B XOR-swizzled chunks),
// 3-stage cp.async pipeline, 8 warps (4x2) each computing 32x64 via m16n8k16.
enum { EPI_STORE_H = 0, EPI_GELU_BIAS = 2, EPI_BIAS_RESID = 3 };

#define GEMM_SMEM 98304   // 3 stages * (A 16KB + B 16KB)

__device__ __forceinline__ uint32_t sw_addr(uint32_t base, int row, int chunk) {
    return base + row * 128 + (((chunk ^ (row & 7)) << 4));
}

template <int MODE>
__device__ __forceinline__ void epi2(int R, int gc, float v0, float v1,
    float* Cf, __half* Ch, const float* bias, const float* resid, int ldc)
{
    if (MODE == EPI_STORE_H) {
        *(__half2*)(Ch + (size_t)R * ldc + gc) = __floats2half2_rn(v0, v1);
    } else if (MODE == EPI_GELU_BIAS) {
        float a0 = v0 + bias[gc], a1 = v1 + bias[gc + 1];
        a0 = 0.5f * a0 * (1.f + erff(a0 * 0.70710678118654752f));
        a1 = 0.5f * a1 * (1.f + erff(a1 * 0.70710678118654752f));
        *(__half2*)(Ch + (size_t)R * ldc + gc) = __floats2half2_rn(a0, a1);
    } else {  // EPI_BIAS_RESID
        float2 rv = *(const float2*)(resid + (size_t)R * 384 + gc);
        *(float2*)(Cf + (size_t)R * ldc + gc) =
            make_float2(v0 + bias[gc] + rv.x, v1 + bias[gc + 1] + rv.y);
    }
}

template <int MODE>
__global__ __launch_bounds__(256) void mma_gemm(
    const __half* __restrict__ Ah, const __half* __restrict__ Bh,
    float* __restrict__ Cf, __half* __restrict__ Ch,
    const float* __restrict__ bias, const float* __restrict__ resid,
    int K, int ldc)
{
    extern __shared__ char smem_raw[];
    uint32_t sA = smem_to_u32(smem_raw);            // 3 x 16KB A stages
    uint32_t sB = sA + 49152;                        // 3 x 16KB B stages

    int tid = threadIdx.x, wid = tid >> 5, lane = tid & 31;
    int brow = blockIdx.y * 128, bcol = blockIdx.x * 128;
    int warpM = wid & 3, warpN = wid >> 2;           // 4x2 warp grid, tile 32x64
    int lg = lane >> 3, lr = lane & 7;               // ldmatrix address group / row

    // stage loader: 128 rows x 64 fp16 per operand, 8 x 16B chunks per row
    auto load_stage = [&](int s, int kc) {
        int k0 = kc << 6;
#pragma unroll
        for (int i = 0; i < 4; i++) {
            int lin = tid + (i << 8);
            int row = lin >> 3, cc = lin & 7;
            int kof = k0 + cc * 8;
            CP_ASYNC16(sw_addr(sA + s * 16384, row, cc),
                       Ah + (size_t)(brow + row) * K + kof);
            CP_ASYNC16(sw_addr(sB + s * 16384, row, cc),
                       Bh + (size_t)(bcol + row) * K + kof);
        }
        CP_COMMIT();
    };

    float acc[2][8][4];
#pragma unroll
    for (int mt = 0; mt < 2; mt++)
#pragma unroll
        for (int nt = 0; nt < 8; nt++)
#pragma unroll
            for (int r = 0; r < 4; r++) acc[mt][nt][r] = 0.f;

    int nstage = K >> 6;
    load_stage(0, 0);
    if (nstage > 1) load_stage(1, 1);

    int buf = 0;
    for (int st = 0; st < nstage; st++) {
        if (st + 2 < nstage) {
            load_stage((buf + 2) % 3, st + 2);
            asm volatile("cp.async.wait_group 2;" ::: "memory");
        } else if (st + 1 < nstage) {
            asm volatile("cp.async.wait_group 1;" ::: "memory");
        } else {
            asm volatile("cp.async.wait_group 0;" ::: "memory");
        }
        __syncthreads();

        uint32_t bA = sA + buf * 16384;
        uint32_t bBs = sB + buf * 16384;
#pragma unroll
        for (int kk = 0; kk < 4; kk++) {
            int c0 = kk * 2;
            uint32_t af[2][4];
#pragma unroll
            for (int mt = 0; mt < 2; mt++) {
                int m0 = warpM * 32 + mt * 16;
                int rowoff = ((lg & 1) ? 8 : 0) + lr;
                int chs = lg >> 1;
                LDMATRIX_X4(af[mt][0], af[mt][1], af[mt][2], af[mt][3],
                            sw_addr(bA, m0 + rowoff, c0 + chs));
            }
            uint32_t bf[4][4];
#pragma unroll
            for (int np = 0; np < 4; np++) {
                int n0 = warpN * 64 + np * 16;
                int rowoff = ((lg >> 1) ? 8 : 0) + lr;
                int chs = lg & 1;
                LDMATRIX_X4(bf[np][0], bf[np][1], bf[np][2], bf[np][3],
                            sw_addr(bBs, n0 + rowoff, c0 + chs));
            }
#pragma unroll
            for (int mt = 0; mt < 2; mt++)
#pragma unroll
                for (int nt = 0; nt < 8; nt++) {
                    uint32_t b0 = bf[nt >> 1][(nt & 1) * 2], b1 = bf[nt >> 1][(nt & 1) * 2 + 1];
                    MMA_F16(acc[mt][nt], af[mt], b0, b1);
                }
        }
        __syncthreads();
        buf = (buf == 2) ? 0 : buf + 1;
    }

    // epilogue straight from registers
#pragma unroll
    for (int mt = 0; mt < 2; mt++)
#pragma unroll
        for (int nt = 0; nt < 8; nt++) {
            int R0 = brow + warpM * 32 + mt * 16 + (lane >> 2);
            int gc = bcol + warpN * 64 + nt * 8 + ((lane & 3) << 1);
            epi2<MODE>(R0,     gc, acc[mt][nt][0], acc[mt][nt][1], Cf, Ch, bias, resid, ldc);
            epi2<MODE>(R0 + 8, gc, acc[mt][nt][2], acc[mt][nt][3], Cf, Ch, bias, resid, ldc);
        }
}

// ======================= attention =======================
// mega qkv row layout [3456]: axial i at cols [i*1152, (i+1)*1152) = [q|k|v] 384 each.
// token row = b*768 + d*256 + h*16 + w.  ao concat layout [M, 1152], axial i at col i*384.

// Axial 0 (T=3, stride 256): one block (128 thr) per (b, hh, ww); all 12 heads.
__global__ void attn3_kernel(const __half* __restrict__ qkv, __half* __restrict__ ao)
{
    __shared__ float s[3][1152];
    __shared__ float p[12][3][3];
    int n = blockIdx.x;
    int b = n >> 8, off = n & 255;
    size_t base = (size_t)b * 768 + off;
    int tid = threadIdx.x;  // 128

    for (int idx = tid; idx < 3 * 1152; idx += 128) {
        int ti = idx / 1152, c = idx % 1152;
        s[ti][c] = __half2float(qkv[(base + (size_t)ti * 256) * 3456 + c]);
    }
    __syncthreads();

    if (tid < 108) {
        int h = tid / 9, r = tid % 9, i = r / 3, j = r % 3;
        float a = 0.f;
#pragma unroll
        for (int d = 0; d < 32; d++) a = fmaf(s[i][h * 32 + d], s[j][384 + h * 32 + d], a);
        p[h][i][j] = a * 0.17677669529663687f;
    }
    __syncthreads();

    if (tid < 36) {
        int h = tid / 3, i = tid % 3;
        float m = fmaxf(p[h][i][0], fmaxf(p[h][i][1], p[h][i][2]));
        float e0 = expf(p[h][i][0] - m), e1 = expf(p[h][i][1] - m), e2 = expf(p[h][i][2] - m);
        float inv = 1.f / (e0 + e1 + e2);
        p[h][i][0] = e0 * inv; p[h][i][1] = e1 * inv; p[h][i][2] = e2 * inv;
    }
    __syncthreads();

    for (int idx = tid; idx < 3 * 384; idx += 128) {
        int i = idx / 384, c = idx % 384, h = c >> 5;
        float o = p[h][i][0] * s[0][768 + c] + p[h][i][1] * s[1][768 + c]
                + p[h][i][2] * s[2][768 + c];
        ao[(base + (size_t)i * 256) * 1152 + c] = __float2half(o);
    }
}

// Axials 1/2 (T=16): one block (256 thr) per sequence; all 12 heads.
// dynamic smem: float s[16][1152] (73728 B) + float p[12][16][16] (12288 B)
#define ATTN16_SMEM (73728 + 12288)
template <int STRIDE, int AX>
__global__ __launch_bounds__(256) void attn16_kernel(const __half* __restrict__ qkv,
                                                     __half* __restrict__ ao)
{
    extern __shared__ float dsm[];
    float (*s)[1152] = (float(*)[1152])dsm;
    float (*p)[16][16] = (float(*)[16][16])(dsm + 16 * 1152);
    int n = blockIdx.x;
    int b = n / 48, r = n % 48;
    int off = (AX == 1) ? ((r >> 4) * 256 + (r & 15)) : ((r >> 4) * 256 + (r & 15) * 16);
    size_t base = (size_t)b * 768 + off;
    const int axoff = AX * 1152;
    int tid = threadIdx.x;  // 256

    for (int idx = tid; idx < 16 * 1152; idx += 256) {
        int ti = idx >> 10 ; // idx / 1152? no — compute properly below
        ti = idx / 1152; int c = idx - ti * 1152;
        s[ti][c] = __half2float(qkv[(base + (size_t)ti * STRIDE) * 3456 + axoff + c]);
    }
    __syncthreads();

    // scores: 12 heads x 16 x 16; each thread does 12
    for (int idx = tid; idx < 3072; idx += 256) {
        int h = idx >> 8, rem = idx & 255, i = rem >> 4, j = rem & 15;
        float a = 0.f;
#pragma unroll
        for (int d = 0; d < 32; d++) a = fmaf(s[i][h * 32 + d], s[j][384 + h * 32 + d], a);
        p[h][i][j] = a * 0.17677669529663687f;
    }
    __syncthreads();

    if (tid < 192) {
        int h = tid >> 4, i = tid & 15;
        float mx = -1e30f;
#pragma unroll
        for (int j = 0; j < 16; j++) mx = fmaxf(mx, p[h][i][j]);
        float e[16], sum = 0.f;
#pragma unroll
        for (int j = 0; j < 16; j++) { e[j] = expf(p[h][i][j] - mx); sum += e[j]; }
        float inv = 1.f / sum;
#pragma unroll
        for (int j = 0; j < 16; j++) p[h][i][j] = e[j] * inv;
    }
    __syncthreads();

    for (int idx = tid; idx < 16 * 384; idx += 256) {
        int i = idx / 384, c = idx - i * 384, h = c >> 5;
        float o = 0.f;
#pragma unroll
        for (int j = 0; j < 16; j++) o = fmaf(p[h][i][j], s[j][768 + c], o);
        ao[(base + (size_t)i * STRIDE) * 1152 + AX * 384 + c] = __float2half(o);
    }
}

// ======================= LayerNorm (warp per token) =======================
template <bool SPLIT>
__global__ void layernorm_kernel(const float* __restrict__ in, float* __restrict__ outf,
                                 __half* __restrict__ outh,
                                 const float* __restrict__ g, const float* __restrict__ b)
{
    int row = blockIdx.x * (blockDim.x >> 5) + (threadIdx.x >> 5);
    int lane = threadIdx.x & 31;
    if (row >= MM) return;
    const float* rp = in + (size_t)row * 384;
    float vals[12];
    float sum = 0.f;
#pragma unroll
    for (int i = 0; i < 12; i++) { vals[i] = rp[lane + i * 32]; sum += vals[i]; }
#pragma unroll
    for (int o = 16; o; o >>= 1) sum += __shfl_xor_sync(0xffffffffu, sum, o);
    float mu = sum * (1.f / 384.f);
    float var = 0.f;
#pragma unroll
    for (int i = 0; i < 12; i++) { float d = vals[i] - mu; var = fmaf(d, d, var); }
#pragma unroll
    for (int o = 16; o; o >>= 1) var += __shfl_xor_sync(0xffffffffu, var, o);
    float inv = rsqrtf(var * (1.f / 384.f) + 1e-5f);
#pragma unroll
    for (int i = 0; i < 12; i++) {
        int c = lane + i * 32;
        float y = (vals[i] - mu) * inv * g[c] + b[c];
        size_t o = (size_t)row * 384 + c;
        outf[o] = y;
        if (SPLIT) outh[o] = __float2half(y);
    }
}

// ======================= launch =======================
extern "C" void kernel_launch(void* const* d_in, const int* in_sizes, int n_in,
                              void* d_out, int out_size)
{
    const float* x = (const float*)d_in[0];
    const float* Wq[3]  = {(const float*)d_in[1], (const float*)d_in[5], (const float*)d_in[9]};
    const float* Wkv[3] = {(const float*)d_in[2], (const float*)d_in[6], (const float*)d_in[10]};
    const float* Wo[3]  = {(const float*)d_in[3], (const float*)d_in[7], (const float*)d_in[11]};
    const float* bo[3]  = {(const float*)d_in[4], (const float*)d_in[8], (const float*)d_in[12]};
    const float* g1  = (const float*)d_in[13];
    const float* be1 = (const float*)d_in[14];
    const float* W1m = (const float*)d_in[15];
    const float* b1m = (const float*)d_in[16];
    const float* W2m = (const float*)d_in[17];
    const float* b2m = (const float*)d_in[18];
    const float* g2  = (const float*)d_in[19];
    const float* be2 = (const float*)d_in[20];
    float* out = (float*)d_out;

    float *t0f, *t1f, *t2f, *bsum;
    __half *t0h, *t2h, *qkvh, *aoh, *wh;
    cudaGetSymbolAddress((void**)&t0f, g_t0f);
    cudaGetSymbolAddress((void**)&t0h, g_t0h);
    cudaGetSymbolAddress((void**)&t1f, g_t1f);
    cudaGetSymbolAddress((void**)&t2f, g_t2f);
    cudaGetSymbolAddress((void**)&t2h, g_t2h);
    cudaGetSymbolAddress((void**)&qkvh, g_qkvh);
    cudaGetSymbolAddress((void**)&aoh, g_aoh);
    cudaGetSymbolAddress((void**)&bsum, g_bsum);
    cudaGetSymbolAddress((void**)&wh, g_wh);

    __half* mlph = qkvh;        // MM x 1536 fp16, qkv dead in MLP phase
    float* t3f = t0f;           // t0f dead after o-proj consumed it as residual

    // weight pool (half elems): mega Wqkv_t [3456,384] | Wo_stack_t [384,1152] | W1_t | W2_t
    const size_t O_OFF  = 1327104;   // 3456*384
    const size_t W1_OFF = 1769472;   // O_OFF + 384*1152
    const size_t W2_OFF = 2359296;   // W1_OFF + 1536*384

    cudaFuncSetAttribute(mma_gemm<EPI_STORE_H>,   cudaFuncAttributeMaxDynamicSharedMemorySize, GEMM_SMEM);
    cudaFuncSetAttribute(mma_gemm<EPI_GELU_BIAS>, cudaFuncAttributeMaxDynamicSharedMemorySize, GEMM_SMEM);
    cudaFuncSetAttribute(mma_gemm<EPI_BIAS_RESID>,cudaFuncAttributeMaxDynamicSharedMemorySize, GEMM_SMEM);
    cudaFuncSetAttribute(attn16_kernel<16, 1>, cudaFuncAttributeMaxDynamicSharedMemorySize, ATTN16_SMEM);
    cudaFuncSetAttribute(attn16_kernel<1, 2>,  cudaFuncAttributeMaxDynamicSharedMemorySize, ATTN16_SMEM);

    dim3 tb(32, 8);
    // weight prep: mega qkv rows i*1152.., stride 384 (K of that GEMM)
    for (int i = 0; i < 3; i++) {
        wconv_kernel<<<dim3(12, 12), tb>>>(Wq[i],  wh + (size_t)(i * 1152) * 384,        384, 384);
        wconv_kernel<<<dim3(24, 12), tb>>>(Wkv[i], wh + (size_t)(i * 1152 + 384) * 384,  768, 384);
        // Wo stacked along K: dest cols [i*384,(i+1)*384) of [384,1152]
        wconv_kernel<<<dim3(12, 12), tb>>>(Wo[i],  wh + O_OFF + i * 384,                 384, 1152);
    }
    wconv_kernel<<<dim3(48, 12), tb>>>(W1m, wh + W1_OFF, 1536, 384);
    wconv_kernel<<<dim3(12, 48), tb>>>(W2m, wh + W2_OFF, 384, 1536);
    bias_sum_kernel<<<1, CC>>>(bo[0], bo[1], bo[2], bsum);

    transpose_in_kernel<<<dim3(SS / 32, CC / 32, BB), tb>>>(x, t0f, t0h);

    // mega qkv projection: N=3456 (all three axials), fp16 out
    mma_gemm<EPI_STORE_H><<<dim3(27, MM / 128), 256, GEMM_SMEM>>>(
        t0h, wh, nullptr, qkvh, nullptr, nullptr, 384, 3456);

    attn3_kernel<<<BB * 256, 128>>>(qkvh, aoh);
    attn16_kernel<16, 1><<<BB * 48, 256, ATTN16_SMEM>>>(qkvh, aoh);
    attn16_kernel<1, 2><<<BB * 48, 256, ATTN16_SMEM>>>(qkvh, aoh);

    // fused o-projection: t1 = t0 + sum_i ao_i @ Wo_i + (bo0+bo1+bo2)
    mma_gemm<EPI_BIAS_RESID><<<dim3(3, MM / 128), 256, GEMM_SMEM>>>(
        aoh, wh + O_OFF, t1f, nullptr, bsum, t0f, 1152, 384);

    layernorm_kernel<true><<<MM / 8, 256>>>(t1f, t2f, t2h, g1, be1);
    mma_gemm<EPI_GELU_BIAS><<<dim3(12, MM / 128), 256, GEMM_SMEM>>>(
        t2h, wh + W1_OFF, nullptr, mlph, b1m, nullptr, 384, 1536);
    mma_gemm<EPI_BIAS_RESID><<<dim3(3, MM / 128), 256, GEMM_SMEM>>>(
        mlph, wh + W2_OFF, t3f, nullptr, b2m, t2f, 1536, 384);
    layernorm_kernel<false><<<MM / 8, 256>>>(t3f, t1f, nullptr, g2, be2);

    transpose_out_kernel<<<dim3(SS / 32, CC / 32, BB), tb>>>(t1f, out);
}

// round 9
// speedup vs baseline: 1.2647x; 1.2647x over previous
#include <cuda_runtime.h>
#include <cuda_fp16.h>
#include <math.h>
#include <stdint.h>

#define BB 128
#define SS 768
#define CC 384
#define MM (BB*SS)      // 98304 tokens

// ======================= low-level helpers (sm_80 ISA only) =======================
__device__ __forceinline__ uint32_t smem_to_u32(const void* smem_ptr) {
    uint32_t addr;
    asm("{ .reg .u64 tmp; cvta.to.shared.u64 tmp, %1; cvt.u32.u64 %0, tmp; }"
        : "=r"(addr) : "l"(smem_ptr));
    return addr;
}

#define CP_ASYNC16(dst32, gptr) \
    asm volatile("cp.async.cg.shared.global [%0], [%1], 16;" :: "r"(dst32), "l"(gptr) : "memory")
#define CP_COMMIT() asm volatile("cp.async.commit_group;" ::: "memory")

#define LDMATRIX_X4(r0, r1, r2, r3, addr) \
    asm volatile("ldmatrix.sync.aligned.m8n8.x4.shared.b16 {%0,%1,%2,%3}, [%4];" \
        : "=r"(r0), "=r"(r1), "=r"(r2), "=r"(r3) : "r"(addr))

#define MMA_F16(d, a, b0, b1) \
    asm volatile("mma.sync.aligned.m16n8k16.row.col.f32.f16.f16.f32 " \
        "{%0,%1,%2,%3}, {%4,%5,%6,%7}, {%8,%9}, {%0,%1,%2,%3};" \
        : "+f"((d)[0]), "+f"((d)[1]), "+f"((d)[2]), "+f"((d)[3]) \
        : "r"((a)[0]), "r"((a)[1]), "r"((a)[2]), "r"((a)[3]), "r"(b0), "r"(b1))

// ======================= scratch (device globals) =======================
__device__ float g_t0f[(size_t)MM * CC];                 // tokens fp32 (resid; also t3)
__device__ __half g_t0h[(size_t)MM * CC];                // tokens fp16 (GEMM A)
__device__ float g_t1f[(size_t)MM * CC];                 // attn-block output / final LN out
__device__ float g_t2f[(size_t)MM * CC];                 // post-LN1 fp32 (resid for MLP2)
__device__ __half g_t2h[(size_t)MM * CC];                // post-LN1 fp16
__device__ __half g_qkvh[(size_t)MM * 3456];             // mega qkv fp16 (aliased by mlp hidden)
__device__ __half g_aoh[(size_t)MM * 1152];              // concat attention outputs fp16
__device__ float g_bsum[CC];                             // bo0+bo1+bo2
#define WTOTAL 2949120
__device__ __half g_wh[WTOTAL];                          // transposed fp16 weights

// ======================= transposes / weight prep =======================
// x (B, C, S) -> t0 (B*S, C) fp32 + fp16
__global__ void transpose_in_kernel(const float* __restrict__ x, float* __restrict__ t0f,
                                    __half* __restrict__ t0h) {
    __shared__ float tile[32][33];
    int b = blockIdx.z;
    int s0 = blockIdx.x * 32;
    int c0 = blockIdx.y * 32;
    int tx = threadIdx.x, ty = threadIdx.y;  // (32,8)
    const float* xp = x + (size_t)b * CC * SS;
#pragma unroll
    for (int yy = 0; yy < 32; yy += 8)
        tile[ty + yy][tx] = xp[(size_t)(c0 + ty + yy) * SS + s0 + tx];
    __syncthreads();
    size_t ob = (size_t)b * SS * CC;
#pragma unroll
    for (int yy = 0; yy < 32; yy += 8) {
        float v = tile[tx][ty + yy];
        size_t o = ob + (size_t)(s0 + ty + yy) * CC + c0 + tx;
        t0f[o] = v;
        t0h[o] = __float2half(v);
    }
}

// t (B*S, C) -> out (B, C, S)
__global__ void transpose_out_kernel(const float* __restrict__ t, float* __restrict__ out) {
    __shared__ float tile[32][33];
    int b = blockIdx.z;
    int s0 = blockIdx.x * 32;
    int c0 = blockIdx.y * 32;
    int tx = threadIdx.x, ty = threadIdx.y;
    const float* tp = t + (size_t)b * SS * CC;
#pragma unroll
    for (int yy = 0; yy < 32; yy += 8)
        tile[ty + yy][tx] = tp[(size_t)(s0 + ty + yy) * CC + c0 + tx];
    __syncthreads();
    float* op = out + (size_t)b * CC * SS;
#pragma unroll
    for (int yy = 0; yy < 32; yy += 8)
        op[(size_t)(c0 + ty + yy) * SS + s0 + tx] = tile[tx][ty + yy];
}

// W [Ksrc, N] fp32 -> T [N, *] fp16 at row-stride dstStride (transpose + convert)
__global__ void wconv_kernel(const float* __restrict__ W, __half* __restrict__ T,
                             int N, int dstStride) {
    __shared__ float tile[32][33];
    int n0 = blockIdx.x * 32;
    int k0 = blockIdx.y * 32;
    int tx = threadIdx.x, ty = threadIdx.y;  // (32,8)
#pragma unroll
    for (int yy = 0; yy < 32; yy += 8)
        tile[ty + yy][tx] = W[(size_t)(k0 + ty + yy) * N + n0 + tx];
    __syncthreads();
#pragma unroll
    for (int yy = 0; yy < 32; yy += 8)
        T[(size_t)(n0 + ty + yy) * dstStride + k0 + tx] = __float2half(tile[tx][ty + yy]);
}

__global__ void bias_sum_kernel(const float* __restrict__ b0, const float* __restrict__ b1,
                                const float* __restrict__ b2, float* __restrict__ bs) {
    int c = threadIdx.x + blockIdx.x * blockDim.x;
    if (c < CC) bs[c] = b0[c] + b1[c] + b2[c];
}

// ======================= fp16 warp-mma GEMM (2-stage cp.async, 64KB smem) =======================
// C[M,N] = A[M,K] * B^T, A [M,K] fp16, B [N,K] fp16 (both K-major).
// Block tile 128x128, BK=64 (one 128B smem row, 8x16B XOR-swizzled chunks),
// 2-stage cp.async pipeline, 8 warps (4x2) each computing 32x64 via m16n8k16.
enum { EPI_STORE_H = 0, EPI_GELU_BIAS = 2, EPI_BIAS_RESID = 3 };

#define GEMM_SMEM 65536   // 2 stages * (A 16KB + B 16KB) -> 3 CTAs/SM

__device__ __forceinline__ uint32_t sw_addr(uint32_t base, int row, int chunk) {
    return base + row * 128 + (((chunk ^ (row & 7)) << 4));
}

template <int MODE>
__device__ __forceinline__ void epi2(int R, int gc, float v0, float v1,
    float* Cf, __half* Ch, const float* bias, const float* resid, int ldc)
{
    if (MODE == EPI_STORE_H) {
        *(__half2*)(Ch + (size_t)R * ldc + gc) = __floats2half2_rn(v0, v1);
    } else if (MODE == EPI_GELU_BIAS) {
        float a0 = v0 + bias[gc], a1 = v1 + bias[gc + 1];
        a0 = 0.5f * a0 * (1.f + erff(a0 * 0.70710678118654752f));
        a1 = 0.5f * a1 * (1.f + erff(a1 * 0.70710678118654752f));
        *(__half2*)(Ch + (size_t)R * ldc + gc) = __floats2half2_rn(a0, a1);
    } else {  // EPI_BIAS_RESID
        float2 rv = *(const float2*)(resid + (size_t)R * 384 + gc);
        *(float2*)(Cf + (size_t)R * ldc + gc) =
            make_float2(v0 + bias[gc] + rv.x, v1 + bias[gc + 1] + rv.y);
    }
}

template <int MODE>
__global__ __launch_bounds__(256) void mma_gemm(
    const __half* __restrict__ Ah, const __half* __restrict__ Bh,
    float* __restrict__ Cf, __half* __restrict__ Ch,
    const float* __restrict__ bias, const float* __restrict__ resid,
    int K, int ldc)
{
    extern __shared__ char smem_raw[];
    uint32_t sA = smem_to_u32(smem_raw);            // 2 x 16KB A stages
    uint32_t sB = sA + 32768;                        // 2 x 16KB B stages

    int tid = threadIdx.x, wid = tid >> 5, lane = tid & 31;
    int brow = blockIdx.y * 128, bcol = blockIdx.x * 128;
    int warpM = wid & 3, warpN = wid >> 2;           // 4x2 warp grid, tile 32x64
    int lg = lane >> 3, lr = lane & 7;               // ldmatrix address group / row

    auto load_stage = [&](int s, int kc) {
        int k0 = kc << 6;
#pragma unroll
        for (int i = 0; i < 4; i++) {
            int lin = tid + (i << 8);
            int row = lin >> 3, cc = lin & 7;
            int kof = k0 + cc * 8;
            CP_ASYNC16(sw_addr(sA + s * 16384, row, cc),
                       Ah + (size_t)(brow + row) * K + kof);
            CP_ASYNC16(sw_addr(sB + s * 16384, row, cc),
                       Bh + (size_t)(bcol + row) * K + kof);
        }
        CP_COMMIT();
    };

    float acc[2][8][4];
#pragma unroll
    for (int mt = 0; mt < 2; mt++)
#pragma unroll
        for (int nt = 0; nt < 8; nt++)
#pragma unroll
            for (int r = 0; r < 4; r++) acc[mt][nt][r] = 0.f;

    int nstage = K >> 6;
    load_stage(0, 0);

    for (int st = 0; st < nstage; st++) {
        if (st + 1 < nstage) {
            load_stage((st + 1) & 1, st + 1);
            asm volatile("cp.async.wait_group 1;" ::: "memory");
        } else {
            asm volatile("cp.async.wait_group 0;" ::: "memory");
        }
        __syncthreads();

        uint32_t bA = sA + (st & 1) * 16384;
        uint32_t bBs = sB + (st & 1) * 16384;
#pragma unroll
        for (int kk = 0; kk < 4; kk++) {
            int c0 = kk * 2;
            uint32_t af[2][4];
#pragma unroll
            for (int mt = 0; mt < 2; mt++) {
                int m0 = warpM * 32 + mt * 16;
                int rowoff = ((lg & 1) ? 8 : 0) + lr;
                int chs = lg >> 1;
                LDMATRIX_X4(af[mt][0], af[mt][1], af[mt][2], af[mt][3],
                            sw_addr(bA, m0 + rowoff, c0 + chs));
            }
            uint32_t bf[4][4];
#pragma unroll
            for (int np = 0; np < 4; np++) {
                int n0 = warpN * 64 + np * 16;
                int rowoff = ((lg >> 1) ? 8 : 0) + lr;
                int chs = lg & 1;
                LDMATRIX_X4(bf[np][0], bf[np][1], bf[np][2], bf[np][3],
                            sw_addr(bBs, n0 + rowoff, c0 + chs));
            }
#pragma unroll
            for (int mt = 0; mt < 2; mt++)
#pragma unroll
                for (int nt = 0; nt < 8; nt++) {
                    uint32_t b0 = bf[nt >> 1][(nt & 1) * 2], b1 = bf[nt >> 1][(nt & 1) * 2 + 1];
                    MMA_F16(acc[mt][nt], af[mt], b0, b1);
                }
        }
        __syncthreads();
    }

    // epilogue straight from registers
#pragma unroll
    for (int mt = 0; mt < 2; mt++)
#pragma unroll
        for (int nt = 0; nt < 8; nt++) {
            int R0 = brow + warpM * 32 + mt * 16 + (lane >> 2);
            int gc = bcol + warpN * 64 + nt * 8 + ((lane & 3) << 1);
            epi2<MODE>(R0,     gc, acc[mt][nt][0], acc[mt][nt][1], Cf, Ch, bias, resid, ldc);
            epi2<MODE>(R0 + 8, gc, acc[mt][nt][2], acc[mt][nt][3], Cf, Ch, bias, resid, ldc);
        }
}

// ======================= attention =======================
// mega qkv row layout [3456]: axial i at cols [i*1152, (i+1)*1152) = [q|k|v] 384 each.
// token row = b*768 + d*256 + h*16 + w.  ao concat layout [M, 1152], axial i at col i*384.

// Axial 0 (T=3, stride 256): one block (128 thr) per (b, hh, ww); all 12 heads.
__global__ void attn3_kernel(const __half* __restrict__ qkv, __half* __restrict__ ao)
{
    __shared__ float s[3][1152];
    __shared__ float p[12][3][3];
    int n = blockIdx.x;
    int b = n >> 8, off = n & 255;
    size_t base = (size_t)b * 768 + off;
    int tid = threadIdx.x;  // 128

    for (int idx = tid; idx < 3 * 1152; idx += 128) {
        int ti = idx / 1152, c = idx % 1152;
        s[ti][c] = __half2float(qkv[(base + (size_t)ti * 256) * 3456 + c]);
    }
    __syncthreads();

    if (tid < 108) {
        int h = tid / 9, r = tid % 9, i = r / 3, j = r % 3;
        float a = 0.f;
#pragma unroll
        for (int d = 0; d < 32; d++) a = fmaf(s[i][h * 32 + d], s[j][384 + h * 32 + d], a);
        p[h][i][j] = a * 0.17677669529663687f;
    }
    __syncthreads();

    if (tid < 36) {
        int h = tid / 3, i = tid % 3;
        float m = fmaxf(p[h][i][0], fmaxf(p[h][i][1], p[h][i][2]));
        float e0 = expf(p[h][i][0] - m), e1 = expf(p[h][i][1] - m), e2 = expf(p[h][i][2] - m);
        float inv = 1.f / (e0 + e1 + e2);
        p[h][i][0] = e0 * inv; p[h][i][1] = e1 * inv; p[h][i][2] = e2 * inv;
    }
    __syncthreads();

    for (int idx = tid; idx < 3 * 384; idx += 128) {
        int i = idx / 384, c = idx % 384, h = c >> 5;
        float o = p[h][i][0] * s[0][768 + c] + p[h][i][1] * s[1][768 + c]
                + p[h][i][2] * s[2][768 + c];
        ao[(base + (size_t)i * 256) * 1152 + c] = __float2half(o);
    }
}

// Axials 1/2 (T=16): one 128-thread block per (sequence, head). Small static smem.
template <int STRIDE, int AX>
__global__ void attn16_kernel(const __half* __restrict__ qkv, __half* __restrict__ ao)
{
    const int T = 16;
    __shared__ float q[T][32], k[T][32], v[T][32], sc[T][T];
    int n = blockIdx.x;
    int head = blockIdx.y;
    int b = n / 48, r = n % 48;
    int off = (AX == 1) ? ((r >> 4) * 256 + (r & 15)) : ((r >> 4) * 256 + (r & 15) * 16);
    size_t base = (size_t)b * 768 + off;
    const int axoff = AX * 1152;
    int tid = threadIdx.x;  // 128

    for (int idx = tid; idx < T * 32; idx += 128) {
        int ti = idx >> 5, d = idx & 31;
        size_t row = (base + (size_t)ti * STRIDE) * 3456 + axoff + head * 32;
        q[ti][d] = __half2float(qkv[row + d]);
        k[ti][d] = __half2float(qkv[row + 384 + d]);
        v[ti][d] = __half2float(qkv[row + 768 + d]);
    }
    __syncthreads();

    for (int idx = tid; idx < T * T; idx += 128) {
        int i = idx >> 4, j = idx & 15;
        float s = 0.f;
#pragma unroll
        for (int d = 0; d < 32; d++) s = fmaf(q[i][d], k[j][d], s);
        sc[i][j] = s * 0.17677669529663687f;
    }
    __syncthreads();

    if (tid < T) {
        float mx = -1e30f;
#pragma unroll
        for (int j = 0; j < T; j++) mx = fmaxf(mx, sc[tid][j]);
        float e[T];
        float sum = 0.f;
#pragma unroll
        for (int j = 0; j < T; j++) { e[j] = expf(sc[tid][j] - mx); sum += e[j]; }
        float inv = 1.f / sum;
#pragma unroll
        for (int j = 0; j < T; j++) sc[tid][j] = e[j] * inv;
    }
    __syncthreads();

    for (int idx = tid; idx < T * 32; idx += 128) {
        int i = idx >> 5, d = idx & 31;
        float o = 0.f;
#pragma unroll
        for (int j = 0; j < T; j++) o = fmaf(sc[i][j], v[j][d], o);
        ao[(base + (size_t)i * STRIDE) * 1152 + AX * 384 + head * 32 + d] = __float2half(o);
    }
}

// ======================= LayerNorm (warp per token) =======================
template <bool SPLIT>
__global__ void layernorm_kernel(const float* __restrict__ in, float* __restrict__ outf,
                                 __half* __restrict__ outh,
                                 const float* __restrict__ g, const float* __restrict__ b)
{
    int row = blockIdx.x * (blockDim.x >> 5) + (threadIdx.x >> 5);
    int lane = threadIdx.x & 31;
    if (row >= MM) return;
    const float* rp = in + (size_t)row * 384;
    float vals[12];
    float sum = 0.f;
#pragma unroll
    for (int i = 0; i < 12; i++) { vals[i] = rp[lane + i * 32]; sum += vals[i]; }
#pragma unroll
    for (int o = 16; o; o >>= 1) sum += __shfl_xor_sync(0xffffffffu, sum, o);
    float mu = sum * (1.f / 384.f);
    float var = 0.f;
#pragma unroll
    for (int i = 0; i < 12; i++) { float d = vals[i] - mu; var = fmaf(d, d, var); }
#pragma unroll
    for (int o = 16; o; o >>= 1) var += __shfl_xor_sync(0xffffffffu, var, o);
    float inv = rsqrtf(var * (1.f / 384.f) + 1e-5f);
#pragma unroll
    for (int i = 0; i < 12; i++) {
        int c = lane + i * 32;
        float y = (vals[i] - mu) * inv * g[c] + b[c];
        size_t o = (size_t)row * 384 + c;
        outf[o] = y;
        if (SPLIT) outh[o] = __float2half(y);
    }
}

// ======================= launch =======================
extern "C" void kernel_launch(void* const* d_in, const int* in_sizes, int n_in,
                              void* d_out, int out_size)
{
    const float* x = (const float*)d_in[0];
    const float* Wq[3]  = {(const float*)d_in[1], (const float*)d_in[5], (const float*)d_in[9]};
    const float* Wkv[3] = {(const float*)d_in[2], (const float*)d_in[6], (const float*)d_in[10]};
    const float* Wo[3]  = {(const float*)d_in[3], (const float*)d_in[7], (const float*)d_in[11]};
    const float* bo[3]  = {(const float*)d_in[4], (const float*)d_in[8], (const float*)d_in[12]};
    const float* g1  = (const float*)d_in[13];
    const float* be1 = (const float*)d_in[14];
    const float* W1m = (const float*)d_in[15];
    const float* b1m = (const float*)d_in[16];
    const float* W2m = (const float*)d_in[17];
    const float* b2m = (const float*)d_in[18];
    const float* g2  = (const float*)d_in[19];
    const float* be2 = (const float*)d_in[20];
    float* out = (float*)d_out;

    float *t0f, *t1f, *t2f, *bsum;
    __half *t0h, *t2h, *qkvh, *aoh, *wh;
    cudaGetSymbolAddress((void**)&t0f, g_t0f);
    cudaGetSymbolAddress((void**)&t0h, g_t0h);
    cudaGetSymbolAddress((void**)&t1f, g_t1f);
    cudaGetSymbolAddress((void**)&t2f, g_t2f);
    cudaGetSymbolAddress((void**)&t2h, g_t2h);
    cudaGetSymbolAddress((void**)&qkvh, g_qkvh);
    cudaGetSymbolAddress((void**)&aoh, g_aoh);
    cudaGetSymbolAddress((void**)&bsum, g_bsum);
    cudaGetSymbolAddress((void**)&wh, g_wh);

    __half* mlph = qkvh;        // MM x 1536 fp16, qkv dead in MLP phase
    float* t3f = t0f;           // t0f dead after o-proj consumed it as residual

    // weight pool (half elems): mega Wqkv_t [3456,384] | Wo_stack_t [384,1152] | W1_t | W2_t
    const size_t O_OFF  = 1327104;   // 3456*384
    const size_t W1_OFF = 1769472;   // O_OFF + 384*1152
    const size_t W2_OFF = 2359296;   // W1_OFF + 1536*384

    cudaFuncSetAttribute(mma_gemm<EPI_STORE_H>,   cudaFuncAttributeMaxDynamicSharedMemorySize, GEMM_SMEM);
    cudaFuncSetAttribute(mma_gemm<EPI_GELU_BIAS>, cudaFuncAttributeMaxDynamicSharedMemorySize, GEMM_SMEM);
    cudaFuncSetAttribute(mma_gemm<EPI_BIAS_RESID>,cudaFuncAttributeMaxDynamicSharedMemorySize, GEMM_SMEM);

    dim3 tb(32, 8);
    // weight prep: mega qkv rows i*1152.., stride 384 (K of that GEMM)
    for (int i = 0; i < 3; i++) {
        wconv_kernel<<<dim3(12, 12), tb>>>(Wq[i],  wh + (size_t)(i * 1152) * 384,        384, 384);
        wconv_kernel<<<dim3(24, 12), tb>>>(Wkv[i], wh + (size_t)(i * 1152 + 384) * 384,  768, 384);
        // Wo stacked along K: dest cols [i*384,(i+1)*384) of [384,1152]
        wconv_kernel<<<dim3(12, 12), tb>>>(Wo[i],  wh + O_OFF + i * 384,                 384, 1152);
    }
    wconv_kernel<<<dim3(48, 12), tb>>>(W1m, wh + W1_OFF, 1536, 384);
    wconv_kernel<<<dim3(12, 48), tb>>>(W2m, wh + W2_OFF, 384, 1536);
    bias_sum_kernel<<<1, CC>>>(bo[0], bo[1], bo[2], bsum);

    transpose_in_kernel<<<dim3(SS / 32, CC / 32, BB), tb>>>(x, t0f, t0h);

    // mega qkv projection: N=3456 (all three axials), fp16 out
    mma_gemm<EPI_STORE_H><<<dim3(27, MM / 128), 256, GEMM_SMEM>>>(
        t0h, wh, nullptr, qkvh, nullptr, nullptr, 384, 3456);

    attn3_kernel<<<BB * 256, 128>>>(qkvh, aoh);
    attn16_kernel<16, 1><<<dim3(BB * 48, 12), 128>>>(qkvh, aoh);
    attn16_kernel<1, 2><<<dim3(BB * 48, 12), 128>>>(qkvh, aoh);

    // fused o-projection: t1 = t0 + sum_i ao_i @ Wo_i + (bo0+bo1+bo2)
    mma_gemm<EPI_BIAS_RESID><<<dim3(3, MM / 128), 256, GEMM_SMEM>>>(
        aoh, wh + O_OFF, t1f, nullptr, bsum, t0f, 1152, 384);

    layernorm_kernel<true><<<MM / 8, 256>>>(t1f, t2f, t2h, g1, be1);
    mma_gemm<EPI_GELU_BIAS><<<dim3(12, MM / 128), 256, GEMM_SMEM>>>(
        t2h, wh + W1_OFF, nullptr, mlph, b1m, nullptr, 384, 1536);
    mma_gemm<EPI_BIAS_RESID><<<dim3(3, MM / 128), 256, GEMM_SMEM>>>(
        mlph, wh + W2_OFF, t3f, nullptr, b2m, t2f, 1536, 384);
    layernorm_kernel<false><<<MM / 8, 256>>>(t3f, t1f, nullptr, g2, be2);

    transpose_out_kernel<<<dim3(SS / 32, CC / 32, BB), tb>>>(t1f, out);
}

// round 10
// speedup vs baseline: 1.2824x; 1.0140x over previous
#include <cuda_runtime.h>
#include <cuda_fp16.h>
#include <math.h>
#include <stdint.h>

#define BB 128
#define SS 768
#define CC 384
#define MM (BB*SS)      // 98304 tokens

// ======================= low-level helpers (sm_80 ISA only) =======================
__device__ __forceinline__ uint32_t smem_to_u32(const void* smem_ptr) {
    uint32_t addr;
    asm("{ .reg .u64 tmp; cvta.to.shared.u64 tmp, %1; cvt.u32.u64 %0, tmp; }"
        : "=r"(addr) : "l"(smem_ptr));
    return addr;
}

#define CP_ASYNC16(dst32, gptr) \
    asm volatile("cp.async.cg.shared.global [%0], [%1], 16;" :: "r"(dst32), "l"(gptr) : "memory")
#define CP_COMMIT() asm volatile("cp.async.commit_group;" ::: "memory")

#define LDMATRIX_X4(r0, r1, r2, r3, addr) \
    asm volatile("ldmatrix.sync.aligned.m8n8.x4.shared.b16 {%0,%1,%2,%3}, [%4];" \
        : "=r"(r0), "=r"(r1), "=r"(r2), "=r"(r3) : "r"(addr))

#define MMA_F16(d, a, b0, b1) \
    asm volatile("mma.sync.aligned.m16n8k16.row.col.f32.f16.f16.f32 " \
        "{%0,%1,%2,%3}, {%4,%5,%6,%7}, {%8,%9}, {%0,%1,%2,%3};" \
        : "+f"((d)[0]), "+f"((d)[1]), "+f"((d)[2]), "+f"((d)[3]) \
        : "r"((a)[0]), "r"((a)[1]), "r"((a)[2]), "r"((a)[3]), "r"(b0), "r"(b1))

// ======================= scratch (device globals) =======================
__device__ float g_t0f[(size_t)MM * CC];                 // tokens fp32 (resid; also t3)
__device__ __half g_t0h[(size_t)MM * CC];                // tokens fp16 (GEMM A)
__device__ float g_t1f[(size_t)MM * CC];                 // attn-block output / final LN out
__device__ float g_t2f[(size_t)MM * CC];                 // post-LN1 fp32 (resid for MLP2)
__device__ __half g_t2h[(size_t)MM * CC];                // post-LN1 fp16
__device__ __half g_qkvh[(size_t)MM * 3456];             // mega qkv fp16 (aliased by mlp hidden)
__device__ __half g_aoh[(size_t)MM * 1152];              // concat attention outputs fp16
#define WTOTAL 2949120
__device__ __half g_wh[WTOTAL];                          // transposed fp16 weights

// ======================= transposes / weight prep =======================
// x (B, C, S) -> t0 (B*S, C) fp32 + fp16
__global__ void transpose_in_kernel(const float* __restrict__ x, float* __restrict__ t0f,
                                    __half* __restrict__ t0h) {
    __shared__ float tile[32][33];
    int b = blockIdx.z;
    int s0 = blockIdx.x * 32;
    int c0 = blockIdx.y * 32;
    int tx = threadIdx.x, ty = threadIdx.y;  // (32,8)
    const float* xp = x + (size_t)b * CC * SS;
#pragma unroll
    for (int yy = 0; yy < 32; yy += 8)
        tile[ty + yy][tx] = xp[(size_t)(c0 + ty + yy) * SS + s0 + tx];
    __syncthreads();
    size_t ob = (size_t)b * SS * CC;
#pragma unroll
    for (int yy = 0; yy < 32; yy += 8) {
        float v = tile[tx][ty + yy];
        size_t o = ob + (size_t)(s0 + ty + yy) * CC + c0 + tx;
        t0f[o] = v;
        t0h[o] = __float2half(v);
    }
}

// t (B*S, C) -> out (B, C, S)
__global__ void transpose_out_kernel(const float* __restrict__ t, float* __restrict__ out) {
    __shared__ float tile[32][33];
    int b = blockIdx.z;
    int s0 = blockIdx.x * 32;
    int c0 = blockIdx.y * 32;
    int tx = threadIdx.x, ty = threadIdx.y;
    const float* tp = t + (size_t)b * SS * CC;
#pragma unroll
    for (int yy = 0; yy < 32; yy += 8)
        tile[ty + yy][tx] = tp[(size_t)(s0 + ty + yy) * CC + c0 + tx];
    __syncthreads();
    float* op = out + (size_t)b * CC * SS;
#pragma unroll
    for (int yy = 0; yy < 32; yy += 8)
        op[(size_t)(c0 + ty + yy) * SS + s0 + tx] = tile[tx][ty + yy];
}

// core transpose+convert: W [Ksrc, N] fp32 -> T [N, *] fp16 with row-stride dstStride
__device__ __forceinline__ void wconv_body(const float* __restrict__ W, __half* __restrict__ T,
                                           int N, int dstStride) {
    __shared__ float tile[32][33];
    int n0 = blockIdx.x * 32;
    int k0 = blockIdx.y * 32;
    int tx = threadIdx.x, ty = threadIdx.y;  // (32,8)
#pragma unroll
    for (int yy = 0; yy < 32; yy += 8)
        tile[ty + yy][tx] = W[(size_t)(k0 + ty + yy) * N + n0 + tx];
    __syncthreads();
#pragma unroll
    for (int yy = 0; yy < 32; yy += 8)
        T[(size_t)(n0 + ty + yy) * dstStride + k0 + tx] = __float2half(tile[tx][ty + yy]);
}

// z-batched over the 3 axial weights (same shape, different src + dst offset)
__global__ void wconv3_kernel(const float* __restrict__ Wa, const float* __restrict__ Wb,
                              const float* __restrict__ Wc, __half* __restrict__ T,
                              size_t zstride, int N, int dstStride) {
    const float* W = (blockIdx.z == 0) ? Wa : (blockIdx.z == 1) ? Wb : Wc;
    wconv_body(W, T + blockIdx.z * zstride, N, dstStride);
}

// W1m [384,1536] and W2m [1536,384] in one launch (z selects; guards trim the grid)
__global__ void wconv12_kernel(const float* __restrict__ W1, __half* __restrict__ T1,
                               const float* __restrict__ W2, __half* __restrict__ T2) {
    if (blockIdx.z == 0) {
        if (blockIdx.y >= 12) return;          // K=384
        wconv_body(W1, T1, 1536, 384);
    } else {
        if (blockIdx.x >= 12) return;          // N=384
        wconv_body(W2, T2, 384, 1536);
    }
}

// ======================= fp16 warp-mma GEMM =======================
// C[M,N] = A[M,K] * B^T, A [M,K] fp16, B [N,K] fp16 (both K-major).
// Block tile 128x128, BK=64, 2-stage cp.async, 4 warps (2x2) each computing 64x64.
enum { EPI_STORE_H = 0, EPI_GELU_BIAS = 2, EPI_BIAS_RESID = 3, EPI_BIAS3_RESID = 4 };

#define GEMM_SMEM 65536   // 2 stages * (A 16KB + B 16KB)

__device__ __forceinline__ uint32_t sw_addr(uint32_t base, int row, int chunk) {
    return base + row * 128 + (((chunk ^ (row & 7)) << 4));
}

template <int MODE>
__device__ __forceinline__ void epi2(int R, int gc, float v0, float v1,
    float* Cf, __half* Ch, const float* bias, const float* bias2, const float* bias3,
    const float* resid, int ldc)
{
    if (MODE == EPI_STORE_H) {
        *(__half2*)(Ch + (size_t)R * ldc + gc) = __floats2half2_rn(v0, v1);
    } else if (MODE == EPI_GELU_BIAS) {
        float a0 = v0 + bias[gc], a1 = v1 + bias[gc + 1];
        a0 = 0.5f * a0 * (1.f + erff(a0 * 0.70710678118654752f));
        a1 = 0.5f * a1 * (1.f + erff(a1 * 0.70710678118654752f));
        *(__half2*)(Ch + (size_t)R * ldc + gc) = __floats2half2_rn(a0, a1);
    } else if (MODE == EPI_BIAS_RESID) {
        float2 rv = *(const float2*)(resid + (size_t)R * 384 + gc);
        *(float2*)(Cf + (size_t)R * ldc + gc) =
            make_float2(v0 + bias[gc] + rv.x, v1 + bias[gc + 1] + rv.y);
    } else {  // EPI_BIAS3_RESID
        float2 rv = *(const float2*)(resid + (size_t)R * 384 + gc);
        float b0s = bias[gc] + bias2[gc] + bias3[gc];
        float b1s = bias[gc + 1] + bias2[gc + 1] + bias3[gc + 1];
        *(float2*)(Cf + (size_t)R * ldc + gc) =
            make_float2(v0 + b0s + rv.x, v1 + b1s + rv.y);
    }
}

template <int MODE>
__global__ __launch_bounds__(128) void mma_gemm(
    const __half* __restrict__ Ah, const __half* __restrict__ Bh,
    float* __restrict__ Cf, __half* __restrict__ Ch,
    const float* __restrict__ bias, const float* __restrict__ bias2,
    const float* __restrict__ bias3, const float* __restrict__ resid,
    int K, int ldc)
{
    extern __shared__ char smem_raw[];
    uint32_t sA = smem_to_u32(smem_raw);            // 2 x 16KB A stages
    uint32_t sB = sA + 32768;                        // 2 x 16KB B stages

    int tid = threadIdx.x, wid = tid >> 5, lane = tid & 31;
    int brow = blockIdx.y * 128, bcol = blockIdx.x * 128;
    int warpM = wid & 1, warpN = wid >> 1;           // 2x2 warp grid, tile 64x64
    int lg = lane >> 3, lr = lane & 7;               // ldmatrix address group / row

    // stage loader: 128 rows x 64 fp16 per operand = 1024 x 16B chunks, 128 threads
    auto load_stage = [&](int s, int kc) {
        int k0 = kc << 6;
#pragma unroll
        for (int i = 0; i < 8; i++) {
            int lin = tid + (i << 7);
            int row = lin >> 3, cc = lin & 7;
            int kof = k0 + cc * 8;
            CP_ASYNC16(sw_addr(sA + s * 16384, row, cc),
                       Ah + (size_t)(brow + row) * K + kof);
            CP_ASYNC16(sw_addr(sB + s * 16384, row, cc),
                       Bh + (size_t)(bcol + row) * K + kof);
        }
        CP_COMMIT();
    };

    float acc[4][8][4];
#pragma unroll
    for (int mt = 0; mt < 4; mt++)
#pragma unroll
        for (int nt = 0; nt < 8; nt++)
#pragma unroll
            for (int r = 0; r < 4; r++) acc[mt][nt][r] = 0.f;

    int nstage = K >> 6;
    load_stage(0, 0);

    for (int st = 0; st < nstage; st++) {
        if (st + 1 < nstage) {
            load_stage((st + 1) & 1, st + 1);
            asm volatile("cp.async.wait_group 1;" ::: "memory");
        } else {
            asm volatile("cp.async.wait_group 0;" ::: "memory");
        }
        __syncthreads();

        uint32_t bA = sA + (st & 1) * 16384;
        uint32_t bBs = sB + (st & 1) * 16384;
#pragma unroll
        for (int kk = 0; kk < 4; kk++) {
            int c0 = kk * 2;
            uint32_t af[4][4];
#pragma unroll
            for (int mt = 0; mt < 4; mt++) {
                int m0 = warpM * 64 + mt * 16;
                int rowoff = ((lg & 1) ? 8 : 0) + lr;
                int chs = lg >> 1;
                LDMATRIX_X4(af[mt][0], af[mt][1], af[mt][2], af[mt][3],
                            sw_addr(bA, m0 + rowoff, c0 + chs));
            }
            uint32_t bf[4][4];
#pragma unroll
            for (int np = 0; np < 4; np++) {
                int n0 = warpN * 64 + np * 16;
                int rowoff = ((lg >> 1) ? 8 : 0) + lr;
                int chs = lg & 1;
                LDMATRIX_X4(bf[np][0], bf[np][1], bf[np][2], bf[np][3],
                            sw_addr(bBs, n0 + rowoff, c0 + chs));
            }
#pragma unroll
            for (int mt = 0; mt < 4; mt++)
#pragma unroll
                for (int nt = 0; nt < 8; nt++) {
                    uint32_t b0 = bf[nt >> 1][(nt & 1) * 2], b1 = bf[nt >> 1][(nt & 1) * 2 + 1];
                    MMA_F16(acc[mt][nt], af[mt], b0, b1);
                }
        }
        __syncthreads();
    }

    // epilogue straight from registers
#pragma unroll
    for (int mt = 0; mt < 4; mt++)
#pragma unroll
        for (int nt = 0; nt < 8; nt++) {
            int R0 = brow + warpM * 64 + mt * 16 + (lane >> 2);
            int gc = bcol + warpN * 64 + nt * 8 + ((lane & 3) << 1);
            epi2<MODE>(R0,     gc, acc[mt][nt][0], acc[mt][nt][1], Cf, Ch, bias, bias2, bias3, resid, ldc);
            epi2<MODE>(R0 + 8, gc, acc[mt][nt][2], acc[mt][nt][3], Cf, Ch, bias, bias2, bias3, resid, ldc);
        }
}

// ======================= attention =======================
// mega qkv row layout [3456]: axial i at cols [i*1152, (i+1)*1152) = [q|k|v] 384 each.
// token row = b*768 + d*256 + h*16 + w.  ao concat layout [M, 1152], axial i at col i*384.

// Axial 0 (T=3, stride 256): one block (128 thr) per (b, hh, ww); all 12 heads.
__global__ void attn3_kernel(const __half* __restrict__ qkv, __half* __restrict__ ao)
{
    __shared__ float s[3][1152];
    __shared__ float p[12][3][3];
    int n = blockIdx.x;
    int b = n >> 8, off = n & 255;
    size_t base = (size_t)b * 768 + off;
    int tid = threadIdx.x;  // 128

    for (int idx = tid; idx < 3 * 1152; idx += 128) {
        int ti = idx / 1152, c = idx % 1152;
        s[ti][c] = __half2float(qkv[(base + (size_t)ti * 256) * 3456 + c]);
    }
    __syncthreads();

    if (tid < 108) {
        int h = tid / 9, r = tid % 9, i = r / 3, j = r % 3;
        float a = 0.f;
#pragma unroll
        for (int d = 0; d < 32; d++) a = fmaf(s[i][h * 32 + d], s[j][384 + h * 32 + d], a);
        p[h][i][j] = a * 0.17677669529663687f;
    }
    __syncthreads();

    if (tid < 36) {
        int h = tid / 3, i = tid % 3;
        float m = fmaxf(p[h][i][0], fmaxf(p[h][i][1], p[h][i][2]));
        float e0 = expf(p[h][i][0] - m), e1 = expf(p[h][i][1] - m), e2 = expf(p[h][i][2] - m);
        float inv = 1.f / (e0 + e1 + e2);
        p[h][i][0] = e0 * inv; p[h][i][1] = e1 * inv; p[h][i][2] = e2 * inv;
    }
    __syncthreads();

    for (int idx = tid; idx < 3 * 384; idx += 128) {
        int i = idx / 384, c = idx % 384, h = c >> 5;
        float o = p[h][i][0] * s[0][768 + c] + p[h][i][1] * s[1][768 + c]
                + p[h][i][2] * s[2][768 + c];
        ao[(base + (size_t)i * 256) * 1152 + c] = __float2half(o);
    }
}

// Axials 1/2 (T=16): one 128-thread block per (sequence, head). Small static smem.
template <int STRIDE, int AX>
__global__ void attn16_kernel(const __half* __restrict__ qkv, __half* __restrict__ ao)
{
    const int T = 16;
    __shared__ float q[T][32], k[T][32], v[T][32], sc[T][T];
    int n = blockIdx.x;
    int head = blockIdx.y;
    int b = n / 48, r = n % 48;
    int off = (AX == 1) ? ((r >> 4) * 256 + (r & 15)) : ((r >> 4) * 256 + (r & 15) * 16);
    size_t base = (size_t)b * 768 + off;
    const int axoff = AX * 1152;
    int tid = threadIdx.x;  // 128

    for (int idx = tid; idx < T * 32; idx += 128) {
        int ti = idx >> 5, d = idx & 31;
        size_t row = (base + (size_t)ti * STRIDE) * 3456 + axoff + head * 32;
        q[ti][d] = __half2float(qkv[row + d]);
        k[ti][d] = __half2float(qkv[row + 384 + d]);
        v[ti][d] = __half2float(qkv[row + 768 + d]);
    }
    __syncthreads();

    for (int idx = tid; idx < T * T; idx += 128) {
        int i = idx >> 4, j = idx & 15;
        float s = 0.f;
#pragma unroll
        for (int d = 0; d < 32; d++) s = fmaf(q[i][d], k[j][d], s);
        sc[i][j] = s * 0.17677669529663687f;
    }
    __syncthreads();

    if (tid < T) {
        float mx = -1e30f;
#pragma unroll
        for (int j = 0; j < T; j++) mx = fmaxf(mx, sc[tid][j]);
        float e[T];
        float sum = 0.f;
#pragma unroll
        for (int j = 0; j < T; j++) { e[j] = expf(sc[tid][j] - mx); sum += e[j]; }
        float inv = 1.f / sum;
#pragma unroll
        for (int j = 0; j < T; j++) sc[tid][j] = e[j] * inv;
    }
    __syncthreads();

    for (int idx = tid; idx < T * 32; idx += 128) {
        int i = idx >> 5, d = idx & 31;
        float o = 0.f;
#pragma unroll
        for (int j = 0; j < T; j++) o = fmaf(sc[i][j], v[j][d], o);
        ao[(base + (size_t)i * STRIDE) * 1152 + AX * 384 + head * 32 + d] = __float2half(o);
    }
}

// ======================= LayerNorm (warp per token) =======================
template <bool SPLIT>
__global__ void layernorm_kernel(const float* __restrict__ in, float* __restrict__ outf,
                                 __half* __restrict__ outh,
                                 const float* __restrict__ g, const float* __restrict__ b)
{
    int row = blockIdx.x * (blockDim.x >> 5) + (threadIdx.x >> 5);
    int lane = threadIdx.x & 31;
    if (row >= MM) return;
    const float* rp = in + (size_t)row * 384;
    float vals[12];
    float sum = 0.f;
#pragma unroll
    for (int i = 0; i < 12; i++) { vals[i] = rp[lane + i * 32]; sum += vals[i]; }
#pragma unroll
    for (int o = 16; o; o >>= 1) sum += __shfl_xor_sync(0xffffffffu, sum, o);
    float mu = sum * (1.f / 384.f);
    float var = 0.f;
#pragma unroll
    for (int i = 0; i < 12; i++) { float d = vals[i] - mu; var = fmaf(d, d, var); }
#pragma unroll
    for (int o = 16; o; o >>= 1) var += __shfl_xor_sync(0xffffffffu, var, o);
    float inv = rsqrtf(var * (1.f / 384.f) + 1e-5f);
#pragma unroll
    for (int i = 0; i < 12; i++) {
        int c = lane + i * 32;
        float y = (vals[i] - mu) * inv * g[c] + b[c];
        size_t o = (size_t)row * 384 + c;
        outf[o] = y;
        if (SPLIT) outh[o] = __float2half(y);
    }
}

// ======================= launch =======================
extern "C" void kernel_launch(void* const* d_in, const int* in_sizes, int n_in,
                              void* d_out, int out_size)
{
    const float* x = (const float*)d_in[0];
    const float* Wq[3]  = {(const float*)d_in[1], (const float*)d_in[5], (const float*)d_in[9]};
    const float* Wkv[3] = {(const float*)d_in[2], (const float*)d_in[6], (const float*)d_in[10]};
    const float* Wo[3]  = {(const float*)d_in[3], (const float*)d_in[7], (const float*)d_in[11]};
    const float* bo[3]  = {(const float*)d_in[4], (const float*)d_in[8], (const float*)d_in[12]};
    const float* g1  = (const float*)d_in[13];
    const float* be1 = (const float*)d_in[14];
    const float* W1m = (const float*)d_in[15];
    const float* b1m = (const float*)d_in[16];
    const float* W2m = (const float*)d_in[17];
    const float* b2m = (const float*)d_in[18];
    const float* g2  = (const float*)d_in[19];
    const float* be2 = (const float*)d_in[20];
    float* out = (float*)d_out;

    float *t0f, *t1f, *t2f;
    __half *t0h, *t2h, *qkvh, *aoh, *wh;
    cudaGetSymbolAddress((void**)&t0f, g_t0f);
    cudaGetSymbolAddress((void**)&t0h, g_t0h);
    cudaGetSymbolAddress((void**)&t1f, g_t1f);
    cudaGetSymbolAddress((void**)&t2f, g_t2f);
    cudaGetSymbolAddress((void**)&t2h, g_t2h);
    cudaGetSymbolAddress((void**)&qkvh, g_qkvh);
    cudaGetSymbolAddress((void**)&aoh, g_aoh);
    cudaGetSymbolAddress((void**)&wh, g_wh);

    __half* mlph = qkvh;        // MM x 1536 fp16, qkv dead in MLP phase
    float* t3f = t0f;           // t0f dead after o-proj consumed it as residual

    // weight pool (half elems): mega Wqkv_t [3456,384] | Wo_stack_t [384,1152] | W1_t | W2_t
    const size_t O_OFF  = 1327104;   // 3456*384
    const size_t W1_OFF = 1769472;   // O_OFF + 384*1152
    const size_t W2_OFF = 2359296;   // W1_OFF + 1536*384
    const size_t QZ = (size_t)1152 * 384;  // 442368, per-axial stride in mega Wqkv

    cudaFuncSetAttribute(mma_gemm<EPI_STORE_H>,    cudaFuncAttributeMaxDynamicSharedMemorySize, GEMM_SMEM);
    cudaFuncSetAttribute(mma_gemm<EPI_GELU_BIAS>,  cudaFuncAttributeMaxDynamicSharedMemorySize, GEMM_SMEM);
    cudaFuncSetAttribute(mma_gemm<EPI_BIAS_RESID>, cudaFuncAttributeMaxDynamicSharedMemorySize, GEMM_SMEM);
    cudaFuncSetAttribute(mma_gemm<EPI_BIAS3_RESID>,cudaFuncAttributeMaxDynamicSharedMemorySize, GEMM_SMEM);

    dim3 tb(32, 8);
    // launches 1-5 (so the mega-qkv GEMM is launch #6 for ncu -s 5 -c 1)
    transpose_in_kernel<<<dim3(SS / 32, CC / 32, BB), tb>>>(x, t0f, t0h);                 // 1
    wconv3_kernel<<<dim3(12, 12, 3), tb>>>(Wq[0], Wq[1], Wq[2], wh, QZ, 384, 384);        // 2
    wconv3_kernel<<<dim3(24, 12, 3), tb>>>(Wkv[0], Wkv[1], Wkv[2],
                                           wh + (size_t)384 * 384, QZ, 768, 384);         // 3
    wconv3_kernel<<<dim3(12, 12, 3), tb>>>(Wo[0], Wo[1], Wo[2], wh + O_OFF, 384, 384, 1152); // 4
    wconv12_kernel<<<dim3(48, 48, 2), tb>>>(W1m, wh + W1_OFF, W2m, wh + W2_OFF);          // 5

    // 6: mega qkv projection, N=3456 (all three axials), fp16 out  <-- profiled launch
    mma_gemm<EPI_STORE_H><<<dim3(27, MM / 128), 128, GEMM_SMEM>>>(
        t0h, wh, nullptr, qkvh, nullptr, nullptr, nullptr, nullptr, 384, 3456);

    attn3_kernel<<<BB * 256, 128>>>(qkvh, aoh);
    attn16_kernel<16, 1><<<dim3(BB * 48, 12), 128>>>(qkvh, aoh);
    attn16_kernel<1, 2><<<dim3(BB * 48, 12), 128>>>(qkvh, aoh);

    // fused o-projection: t1 = t0 + sum_i ao_i @ Wo_i + (bo0+bo1+bo2)
    mma_gemm<EPI_BIAS3_RESID><<<dim3(3, MM / 128), 128, GEMM_SMEM>>>(
        aoh, wh + O_OFF, t1f, nullptr, bo[0], bo[1], bo[2], t0f, 1152, 384);

    layernorm_kernel<true><<<MM / 8, 256>>>(t1f, t2f, t2h, g1, be1);
    mma_gemm<EPI_GELU_BIAS><<<dim3(12, MM / 128), 128, GEMM_SMEM>>>(
        t2h, wh + W1_OFF, nullptr, mlph, b1m, nullptr, nullptr, nullptr, 384, 1536);
    mma_gemm<EPI_BIAS_RESID><<<dim3(3, MM / 128), 128, GEMM_SMEM>>>(
        mlph, wh + W2_OFF, t3f, nullptr, b2m, nullptr, nullptr, t2f, 1536, 384);
    layernorm_kernel<false><<<MM / 8, 256>>>(t3f, t1f, nullptr, g2, be2);

    transpose_out_kernel<<<dim3(SS / 32, CC / 32, BB), tb>>>(t1f, out);
}

// round 11
// speedup vs baseline: 1.2995x; 1.0134x over previous
#include <cuda_runtime.h>
#include <cuda_fp16.h>
#include <math.h>
#include <stdint.h>

#define BB 128
#define SS 768
#define CC 384
#define MM (BB*SS)      // 98304 tokens

// ======================= low-level helpers (sm_80 ISA only) =======================
__device__ __forceinline__ uint32_t smem_to_u32(const void* smem_ptr) {
    uint32_t addr;
    asm("{ .reg .u64 tmp; cvta.to.shared.u64 tmp, %1; cvt.u32.u64 %0, tmp; }"
        : "=r"(addr) : "l"(smem_ptr));
    return addr;
}

#define CP_ASYNC16(dst32, gptr) \
    asm volatile("cp.async.cg.shared.global [%0], [%1], 16;" :: "r"(dst32), "l"(gptr) : "memory")
#define CP_COMMIT() asm volatile("cp.async.commit_group;" ::: "memory")

#define LDMATRIX_X4(r0, r1, r2, r3, addr) \
    asm volatile("ldmatrix.sync.aligned.m8n8.x4.shared.b16 {%0,%1,%2,%3}, [%4];" \
        : "=r"(r0), "=r"(r1), "=r"(r2), "=r"(r3) : "r"(addr))

#define MMA_F16(d, a, b0, b1) \
    asm volatile("mma.sync.aligned.m16n8k16.row.col.f32.f16.f16.f32 " \
        "{%0,%1,%2,%3}, {%4,%5,%6,%7}, {%8,%9}, {%0,%1,%2,%3};" \
        : "+f"((d)[0]), "+f"((d)[1]), "+f"((d)[2]), "+f"((d)[3]) \
        : "r"((a)[0]), "r"((a)[1]), "r"((a)[2]), "r"((a)[3]), "r"(b0), "r"(b1))

// ======================= scratch (device globals) =======================
__device__ __half g_t0h[(size_t)MM * CC];                // tokens fp16 (GEMM A + residual)
__device__ float g_t1f[(size_t)MM * CC];                 // pre-LN1 / pre-LN2 / final LN out
__device__ __half g_t2h[(size_t)MM * CC];                // post-LN1 fp16 (A + residual for MLP)
__device__ __half g_qkvh[(size_t)MM * 3456];             // mega qkv fp16 (aliased by mlp hidden)
__device__ __half g_aoh[(size_t)MM * 1152];              // concat attention outputs fp16
#define WTOTAL 2949120
__device__ __half g_wh[WTOTAL];                          // transposed fp16 weights

// ======================= transposes / weight prep =======================
// x (B, C, S) -> t0h (B*S, C) fp16
__global__ void transpose_in_kernel(const float* __restrict__ x, __half* __restrict__ t0h) {
    __shared__ float tile[32][33];
    int b = blockIdx.z;
    int s0 = blockIdx.x * 32;
    int c0 = blockIdx.y * 32;
    int tx = threadIdx.x, ty = threadIdx.y;  // (32,8)
    const float* xp = x + (size_t)b * CC * SS;
#pragma unroll
    for (int yy = 0; yy < 32; yy += 8)
        tile[ty + yy][tx] = xp[(size_t)(c0 + ty + yy) * SS + s0 + tx];
    __syncthreads();
    size_t ob = (size_t)b * SS * CC;
#pragma unroll
    for (int yy = 0; yy < 32; yy += 8)
        t0h[ob + (size_t)(s0 + ty + yy) * CC + c0 + tx] = __float2half(tile[tx][ty + yy]);
}

// t (B*S, C) fp32 -> out (B, C, S)
__global__ void transpose_out_kernel(const float* __restrict__ t, float* __restrict__ out) {
    __shared__ float tile[32][33];
    int b = blockIdx.z;
    int s0 = blockIdx.x * 32;
    int c0 = blockIdx.y * 32;
    int tx = threadIdx.x, ty = threadIdx.y;
    const float* tp = t + (size_t)b * SS * CC;
#pragma unroll
    for (int yy = 0; yy < 32; yy += 8)
        tile[ty + yy][tx] = tp[(size_t)(s0 + ty + yy) * CC + c0 + tx];
    __syncthreads();
    float* op = out + (size_t)b * CC * SS;
#pragma unroll
    for (int yy = 0; yy < 32; yy += 8)
        op[(size_t)(c0 + ty + yy) * SS + s0 + tx] = tile[tx][ty + yy];
}

// core transpose+convert: W [Ksrc, N] fp32 -> T [N, *] fp16 with row-stride dstStride
__device__ __forceinline__ void wconv_body(const float* __restrict__ W, __half* __restrict__ T,
                                           int N, int dstStride) {
    __shared__ float tile[32][33];
    int n0 = blockIdx.x * 32;
    int k0 = blockIdx.y * 32;
    int tx = threadIdx.x, ty = threadIdx.y;  // (32,8)
#pragma unroll
    for (int yy = 0; yy < 32; yy += 8)
        tile[ty + yy][tx] = W[(size_t)(k0 + ty + yy) * N + n0 + tx];
    __syncthreads();
#pragma unroll
    for (int yy = 0; yy < 32; yy += 8)
        T[(size_t)(n0 + ty + yy) * dstStride + k0 + tx] = __float2half(tile[tx][ty + yy]);
}

__global__ void wconv3_kernel(const float* __restrict__ Wa, const float* __restrict__ Wb,
                              const float* __restrict__ Wc, __half* __restrict__ T,
                              size_t zstride, int N, int dstStride) {
    const float* W = (blockIdx.z == 0) ? Wa : (blockIdx.z == 1) ? Wb : Wc;
    wconv_body(W, T + blockIdx.z * zstride, N, dstStride);
}

__global__ void wconv12_kernel(const float* __restrict__ W1, __half* __restrict__ T1,
                               const float* __restrict__ W2, __half* __restrict__ T2) {
    if (blockIdx.z == 0) {
        if (blockIdx.y >= 12) return;          // K=384
        wconv_body(W1, T1, 1536, 384);
    } else {
        if (blockIdx.x >= 12) return;          // N=384
        wconv_body(W2, T2, 384, 1536);
    }
}

// ======================= fp16 warp-mma GEMM =======================
// C[M,N] = A[M,K] * B^T, A [M,K] fp16, B [N,K] fp16 (both K-major).
// Block tile 128x128, BK=64, 2-stage cp.async, 4 warps (2x2) each computing 64x64.
enum { EPI_STORE_H = 0, EPI_GELU_BIAS = 2, EPI_BIAS_RESID = 3, EPI_BIAS3_RESID = 4 };

#define GEMM_SMEM 65536   // 2 stages * (A 16KB + B 16KB)

__device__ __forceinline__ uint32_t sw_addr(uint32_t base, int row, int chunk) {
    return base + row * 128 + (((chunk ^ (row & 7)) << 4));
}

template <int MODE>
__device__ __forceinline__ void epi2(int R, int gc, float v0, float v1,
    float* Cf, __half* Ch, const float* bias, const float* bias2, const float* bias3,
    const __half* residh, int ldc)
{
    if (MODE == EPI_STORE_H) {
        *(__half2*)(Ch + (size_t)R * ldc + gc) = __floats2half2_rn(v0, v1);
    } else if (MODE == EPI_GELU_BIAS) {
        float a0 = v0 + bias[gc], a1 = v1 + bias[gc + 1];
        a0 = 0.5f * a0 * (1.f + erff(a0 * 0.70710678118654752f));
        a1 = 0.5f * a1 * (1.f + erff(a1 * 0.70710678118654752f));
        *(__half2*)(Ch + (size_t)R * ldc + gc) = __floats2half2_rn(a0, a1);
    } else if (MODE == EPI_BIAS_RESID) {
        __half2 rh = *(const __half2*)(residh + (size_t)R * 384 + gc);
        float2 rv = __half22float2(rh);
        *(float2*)(Cf + (size_t)R * ldc + gc) =
            make_float2(v0 + bias[gc] + rv.x, v1 + bias[gc + 1] + rv.y);
    } else {  // EPI_BIAS3_RESID
        __half2 rh = *(const __half2*)(residh + (size_t)R * 384 + gc);
        float2 rv = __half22float2(rh);
        float b0s = bias[gc] + bias2[gc] + bias3[gc];
        float b1s = bias[gc + 1] + bias2[gc + 1] + bias3[gc + 1];
        *(float2*)(Cf + (size_t)R * ldc + gc) =
            make_float2(v0 + b0s + rv.x, v1 + b1s + rv.y);
    }
}

template <int MODE>
__global__ __launch_bounds__(128) void mma_gemm(
    const __half* __restrict__ Ah, const __half* __restrict__ Bh,
    float* __restrict__ Cf, __half* __restrict__ Ch,
    const float* __restrict__ bias, const float* __restrict__ bias2,
    const float* __restrict__ bias3, const __half* __restrict__ residh,
    int K, int ldc)
{
    extern __shared__ char smem_raw[];
    uint32_t sA = smem_to_u32(smem_raw);            // 2 x 16KB A stages
    uint32_t sB = sA + 32768;                        // 2 x 16KB B stages

    int tid = threadIdx.x, wid = tid >> 5, lane = tid & 31;
    int brow = blockIdx.y * 128, bcol = blockIdx.x * 128;
    int warpM = wid & 1, warpN = wid >> 1;           // 2x2 warp grid, tile 64x64
    int lg = lane >> 3, lr = lane & 7;               // ldmatrix address group / row

    auto load_stage = [&](int s, int kc) {
        int k0 = kc << 6;
#pragma unroll
        for (int i = 0; i < 8; i++) {
            int lin = tid + (i << 7);
            int row = lin >> 3, cc = lin & 7;
            int kof = k0 + cc * 8;
            CP_ASYNC16(sw_addr(sA + s * 16384, row, cc),
                       Ah + (size_t)(brow + row) * K + kof);
            CP_ASYNC16(sw_addr(sB + s * 16384, row, cc),
                       Bh + (size_t)(bcol + row) * K + kof);
        }
        CP_COMMIT();
    };

    float acc[4][8][4];
#pragma unroll
    for (int mt = 0; mt < 4; mt++)
#pragma unroll
        for (int nt = 0; nt < 8; nt++)
#pragma unroll
            for (int r = 0; r < 4; r++) acc[mt][nt][r] = 0.f;

    int nstage = K >> 6;
    load_stage(0, 0);

    for (int st = 0; st < nstage; st++) {
        if (st + 1 < nstage) {
            load_stage((st + 1) & 1, st + 1);
            asm volatile("cp.async.wait_group 1;" ::: "memory");
        } else {
            asm volatile("cp.async.wait_group 0;" ::: "memory");
        }
        __syncthreads();

        uint32_t bA = sA + (st & 1) * 16384;
        uint32_t bBs = sB + (st & 1) * 16384;
#pragma unroll
        for (int kk = 0; kk < 4; kk++) {
            int c0 = kk * 2;
            uint32_t af[4][4];
#pragma unroll
            for (int mt = 0; mt < 4; mt++) {
                int m0 = warpM * 64 + mt * 16;
                int rowoff = ((lg & 1) ? 8 : 0) + lr;
                int chs = lg >> 1;
                LDMATRIX_X4(af[mt][0], af[mt][1], af[mt][2], af[mt][3],
                            sw_addr(bA, m0 + rowoff, c0 + chs));
            }
            uint32_t bf[4][4];
#pragma unroll
            for (int np = 0; np < 4; np++) {
                int n0 = warpN * 64 + np * 16;
                int rowoff = ((lg >> 1) ? 8 : 0) + lr;
                int chs = lg & 1;
                LDMATRIX_X4(bf[np][0], bf[np][1], bf[np][2], bf[np][3],
                            sw_addr(bBs, n0 + rowoff, c0 + chs));
            }
#pragma unroll
            for (int mt = 0; mt < 4; mt++)
#pragma unroll
                for (int nt = 0; nt < 8; nt++) {
                    uint32_t b0 = bf[nt >> 1][(nt & 1) * 2], b1 = bf[nt >> 1][(nt & 1) * 2 + 1];
                    MMA_F16(acc[mt][nt], af[mt], b0, b1);
                }
        }
        __syncthreads();
    }

    // epilogue straight from registers
#pragma unroll
    for (int mt = 0; mt < 4; mt++)
#pragma unroll
        for (int nt = 0; nt < 8; nt++) {
            int R0 = brow + warpM * 64 + mt * 16 + (lane >> 2);
            int gc = bcol + warpN * 64 + nt * 8 + ((lane & 3) << 1);
            epi2<MODE>(R0,     gc, acc[mt][nt][0], acc[mt][nt][1], Cf, Ch, bias, bias2, bias3, residh, ldc);
            epi2<MODE>(R0 + 8, gc, acc[mt][nt][2], acc[mt][nt][3], Cf, Ch, bias, bias2, bias3, residh, ldc);
        }
}

// ======================= attention (single merged launch) =======================
// mega qkv row layout [3456]: axial i at cols [i*1152, (i+1)*1152) = [q|k|v] 384 each.
// token row = b*768 + d*256 + h*16 + w.  ao concat layout [M, 1152], axial i at col i*384.

struct A3S { float s[3][1152]; float p[12][3][3]; };
struct A16S { float q[16][32]; float k[16][32]; float v[16][32]; float sc[16][16]; };

__device__ void attn3_body(const __half* __restrict__ qkv, __half* __restrict__ ao,
                           int n, A3S* sm)
{
    int b = n >> 8, off = n & 255;
    size_t base = (size_t)b * 768 + off;
    int tid = threadIdx.x;  // 128

    for (int idx = tid; idx < 3 * 1152; idx += 128) {
        int ti = idx / 1152, c = idx % 1152;
        sm->s[ti][c] = __half2float(qkv[(base + (size_t)ti * 256) * 3456 + c]);
    }
    __syncthreads();

    if (tid < 108) {
        int h = tid / 9, r = tid % 9, i = r / 3, j = r % 3;
        float a = 0.f;
#pragma unroll
        for (int d = 0; d < 32; d++)
            a = fmaf(sm->s[i][h * 32 + d], sm->s[j][384 + h * 32 + d], a);
        sm->p[h][i][j] = a * 0.17677669529663687f;
    }
    __syncthreads();

    if (tid < 36) {
        int h = tid / 3, i = tid % 3;
        float m = fmaxf(sm->p[h][i][0], fmaxf(sm->p[h][i][1], sm->p[h][i][2]));
        float e0 = expf(sm->p[h][i][0] - m), e1 = expf(sm->p[h][i][1] - m), e2 = expf(sm->p[h][i][2] - m);
        float inv = 1.f / (e0 + e1 + e2);
        sm->p[h][i][0] = e0 * inv; sm->p[h][i][1] = e1 * inv; sm->p[h][i][2] = e2 * inv;
    }
    __syncthreads();

    for (int idx = tid; idx < 3 * 384; idx += 128) {
        int i = idx / 384, c = idx % 384, h = c >> 5;
        float o = sm->p[h][i][0] * sm->s[0][768 + c] + sm->p[h][i][1] * sm->s[1][768 + c]
                + sm->p[h][i][2] * sm->s[2][768 + c];
        ao[(base + (size_t)i * 256) * 1152 + c] = __float2half(o);
    }
}

template <int STRIDE, int AX>
__device__ void attn16_body(const __half* __restrict__ qkv, __half* __restrict__ ao,
                            int m, A16S* sm)
{
    const int T = 16;
    int head = m / 6144;           // grid slice: 6144 sequences x 12 heads
    int n = m - head * 6144;
    int b = n / 48, r = n % 48;
    int off = (AX == 1) ? ((r >> 4) * 256 + (r & 15)) : ((r >> 4) * 256 + (r & 15) * 16);
    size_t base = (size_t)b * 768 + off;
    const int axoff = AX * 1152;
    int tid = threadIdx.x;  // 128

    for (int idx = tid; idx < T * 32; idx += 128) {
        int ti = idx >> 5, d = idx & 31;
        size_t row = (base + (size_t)ti * STRIDE) * 3456 + axoff + head * 32;
        sm->q[ti][d] = __half2float(qkv[row + d]);
        sm->k[ti][d] = __half2float(qkv[row + 384 + d]);
        sm->v[ti][d] = __half2float(qkv[row + 768 + d]);
    }
    __syncthreads();

    for (int idx = tid; idx < T * T; idx += 128) {
        int i = idx >> 4, j = idx & 15;
        float s = 0.f;
#pragma unroll
        for (int d = 0; d < 32; d++) s = fmaf(sm->q[i][d], sm->k[j][d], s);
        sm->sc[i][j] = s * 0.17677669529663687f;
    }
    __syncthreads();

    if (tid < T) {
        float mx = -1e30f;
#pragma unroll
        for (int j = 0; j < T; j++) mx = fmaxf(mx, sm->sc[tid][j]);
        float e[T];
        float sum = 0.f;
#pragma unroll
        for (int j = 0; j < T; j++) { e[j] = expf(sm->sc[tid][j] - mx); sum += e[j]; }
        float inv = 1.f / sum;
#pragma unroll
        for (int j = 0; j < T; j++) sm->sc[tid][j] = e[j] * inv;
    }
    __syncthreads();

    for (int idx = tid; idx < T * 32; idx += 128) {
        int i = idx >> 5, d = idx & 31;
        float o = 0.f;
#pragma unroll
        for (int j = 0; j < T; j++) o = fmaf(sm->sc[i][j], sm->v[j][d], o);
        ao[(base + (size_t)i * STRIDE) * 1152 + AX * 384 + head * 32 + d] = __float2half(o);
    }
}

// merged: [0,32768) attn3; [32768,106496) AX=1; [106496,180224) AX=2
__global__ __launch_bounds__(128) void attn_all_kernel(const __half* __restrict__ qkv,
                                                       __half* __restrict__ ao)
{
    __shared__ __align__(16) char smraw[sizeof(A3S)];
    int bid = blockIdx.x;
    if (bid < 32768) {
        attn3_body(qkv, ao, bid, (A3S*)smraw);
    } else if (bid < 106496) {
        attn16_body<16, 1>(qkv, ao, bid - 32768, (A16S*)smraw);
    } else {
        attn16_body<1, 2>(qkv, ao, bid - 106496, (A16S*)smraw);
    }
}

// ======================= LayerNorm (warp per token) =======================
template <bool F32OUT, bool F16OUT>
__global__ void layernorm_kernel(const float* __restrict__ in, float* __restrict__ outf,
                                 __half* __restrict__ outh,
                                 const float* __restrict__ g, const float* __restrict__ b)
{
    int row = blockIdx.x * (blockDim.x >> 5) + (threadIdx.x >> 5);
    int lane = threadIdx.x & 31;
    if (row >= MM) return;
    const float* rp = in + (size_t)row * 384;
    float vals[12];
    float sum = 0.f;
#pragma unroll
    for (int i = 0; i < 12; i++) { vals[i] = rp[lane + i * 32]; sum += vals[i]; }
#pragma unroll
    for (int o = 16; o; o >>= 1) sum += __shfl_xor_sync(0xffffffffu, sum, o);
    float mu = sum * (1.f / 384.f);
    float var = 0.f;
#pragma unroll
    for (int i = 0; i < 12; i++) { float d = vals[i] - mu; var = fmaf(d, d, var); }
#pragma unroll
    for (int o = 16; o; o >>= 1) var += __shfl_xor_sync(0xffffffffu, var, o);
    float inv = rsqrtf(var * (1.f / 384.f) + 1e-5f);
#pragma unroll
    for (int i = 0; i < 12; i++) {
        int c = lane + i * 32;
        float y = (vals[i] - mu) * inv * g[c] + b[c];
        size_t o = (size_t)row * 384 + c;
        if (F32OUT) outf[o] = y;
        if (F16OUT) outh[o] = __float2half(y);
    }
}

// ======================= launch =======================
extern "C" void kernel_launch(void* const* d_in, const int* in_sizes, int n_in,
                              void* d_out, int out_size)
{
    const float* x = (const float*)d_in[0];
    const float* Wq[3]  = {(const float*)d_in[1], (const float*)d_in[5], (const float*)d_in[9]};
    const float* Wkv[3] = {(const float*)d_in[2], (const float*)d_in[6], (const float*)d_in[10]};
    const float* Wo[3]  = {(const float*)d_in[3], (const float*)d_in[7], (const float*)d_in[11]};
    const float* bo[3]  = {(const float*)d_in[4], (const float*)d_in[8], (const float*)d_in[12]};
    const float* g1  = (const float*)d_in[13];
    const float* be1 = (const float*)d_in[14];
    const float* W1m = (const float*)d_in[15];
    const float* b1m = (const float*)d_in[16];
    const float* W2m = (const float*)d_in[17];
    const float* b2m = (const float*)d_in[18];
    const float* g2  = (const float*)d_in[19];
    const float* be2 = (const float*)d_in[20];
    float* out = (float*)d_out;

    float* t1f;
    __half *t0h, *t2h, *qkvh, *aoh, *wh;
    cudaGetSymbolAddress((void**)&t0h, g_t0h);
    cudaGetSymbolAddress((void**)&t1f, g_t1f);
    cudaGetSymbolAddress((void**)&t2h, g_t2h);
    cudaGetSymbolAddress((void**)&qkvh, g_qkvh);
    cudaGetSymbolAddress((void**)&aoh, g_aoh);
    cudaGetSymbolAddress((void**)&wh, g_wh);

    __half* mlph = qkvh;        // MM x 1536 fp16, qkv dead in MLP phase

    // weight pool (half elems): mega Wqkv_t [3456,384] | Wo_stack_t [384,1152] | W1_t | W2_t
    const size_t O_OFF  = 1327104;   // 3456*384
    const size_t W1_OFF = 1769472;   // O_OFF + 384*1152
    const size_t W2_OFF = 2359296;   // W1_OFF + 1536*384
    const size_t QZ = (size_t)1152 * 384;  // per-axial stride in mega Wqkv

    cudaFuncSetAttribute(mma_gemm<EPI_STORE_H>,    cudaFuncAttributeMaxDynamicSharedMemorySize, GEMM_SMEM);
    cudaFuncSetAttribute(mma_gemm<EPI_GELU_BIAS>,  cudaFuncAttributeMaxDynamicSharedMemorySize, GEMM_SMEM);
    cudaFuncSetAttribute(mma_gemm<EPI_BIAS_RESID>, cudaFuncAttributeMaxDynamicSharedMemorySize, GEMM_SMEM);
    cudaFuncSetAttribute(mma_gemm<EPI_BIAS3_RESID>,cudaFuncAttributeMaxDynamicSharedMemorySize, GEMM_SMEM);

    dim3 tb(32, 8);
    transpose_in_kernel<<<dim3(SS / 32, CC / 32, BB), tb>>>(x, t0h);                      // 1
    wconv3_kernel<<<dim3(12, 12, 3), tb>>>(Wq[0], Wq[1], Wq[2], wh, QZ, 384, 384);        // 2
    wconv3_kernel<<<dim3(24, 12, 3), tb>>>(Wkv[0], Wkv[1], Wkv[2],
                                           wh + (size_t)384 * 384, QZ, 768, 384);         // 3
    wconv3_kernel<<<dim3(12, 12, 3), tb>>>(Wo[0], Wo[1], Wo[2], wh + O_OFF, 384, 384, 1152); // 4
    wconv12_kernel<<<dim3(48, 48, 2), tb>>>(W1m, wh + W1_OFF, W2m, wh + W2_OFF);          // 5

    // 6: mega qkv projection, N=3456 (all three axials), fp16 out
    mma_gemm<EPI_STORE_H><<<dim3(27, MM / 128), 128, GEMM_SMEM>>>(
        t0h, wh, nullptr, qkvh, nullptr, nullptr, nullptr, nullptr, 384, 3456);

    // 7: all three axial attentions in one launch
    attn_all_kernel<<<180224, 128>>>(qkvh, aoh);

    // 8: fused o-projection: t1 = t0 + sum_i ao_i @ Wo_i + (bo0+bo1+bo2)  (resid fp16)
    mma_gemm<EPI_BIAS3_RESID><<<dim3(3, MM / 128), 128, GEMM_SMEM>>>(
        aoh, wh + O_OFF, t1f, nullptr, bo[0], bo[1], bo[2], t0h, 1152, 384);

    // 9: LN1 -> fp16 only
    layernorm_kernel<false, true><<<MM / 8, 256>>>(t1f, nullptr, t2h, g1, be1);
    // 10: MLP1 (GELU+bias) -> fp16 hidden
    mma_gemm<EPI_GELU_BIAS><<<dim3(12, MM / 128), 128, GEMM_SMEM>>>(
        t2h, wh + W1_OFF, nullptr, mlph, b1m, nullptr, nullptr, nullptr, 384, 1536);
    // 11: MLP2 + bias + resid(t2h fp16) -> t1f fp32 (t1f dead after LN1 read)
    mma_gemm<EPI_BIAS_RESID><<<dim3(3, MM / 128), 128, GEMM_SMEM>>>(
        mlph, wh + W2_OFF, t1f, nullptr, b2m, nullptr, nullptr, t2h, 1536, 384);
    // 12: LN2 in-place on t1f (row-local, safe)
    layernorm_kernel<true, false><<<MM / 8, 256>>>(t1f, t1f, nullptr, g2, be2);

    transpose_out_kernel<<<dim3(SS / 32, CC / 32, BB), tb>>>(t1f, out);
}